// round 13
// baseline (speedup 1.0000x reference)
#include <cuda_runtime.h>
#include <cuda_fp16.h>
#include <cstdint>

#define NR0 4096
#define NR1 8192
#define NR2 4096
#define NT  16384     // NR0+NR1+NR2
#define C   64
#define OUTC 32
#define NB  64

// fp16 copies of the L matrices (written once by dinv_conv_kernel)
#define LBF_OFF0 0
#define LBF_OFF1 ((size_t)NR0 * NR0)
#define LBF_OFF2 (LBF_OFF1 + (size_t)NR1 * NR1)
#define LBF_TOTAL (LBF_OFF2 + (size_t)NR2 * NR2)

// ---- scratch (device globals; no allocation allowed) ----
__device__ float    g_dinv[NT];
__device__ uint16_t g_Lh[LBF_TOTAL];    // fp16 L
__device__ uint16_t g_zh[C * NT];       // fp16 z^T [C][NT] (K-major B operand)
__device__ float    g_xA[NT * C];       // layer outputs (pre-relu; consumers apply relu)
__device__ float    g_xB[NT * C];
__device__ float    g_pooled[3 * NB * C];

// ============================================================
// helpers
// ============================================================
__device__ __forceinline__ uint32_t pack_f16(float lo, float hi) {
    __half2 h = __floats2half2_rn(lo, hi);   // lo -> low 16 bits
    return *(uint32_t*)&h;
}
__device__ __forceinline__ void mma_f16(float* c, const uint32_t* a, const uint32_t* b) {
    asm volatile("mma.sync.aligned.m16n8k16.row.col.f32.f16.f16.f32 "
        "{%0,%1,%2,%3}, {%4,%5,%6,%7}, {%8,%9}, {%0,%1,%2,%3};"
        : "+f"(c[0]), "+f"(c[1]), "+f"(c[2]), "+f"(c[3])
        : "r"(a[0]), "r"(a[1]), "r"(a[2]), "r"(a[3]), "r"(b[0]), "r"(b[1]));
}
__device__ __forceinline__ void ldsm_x4(uint32_t& r0, uint32_t& r1, uint32_t& r2,
                                        uint32_t& r3, uint32_t addr) {
    asm volatile("ldmatrix.sync.aligned.m8n8.x4.shared.b16 {%0,%1,%2,%3}, [%4];"
                 : "=r"(r0), "=r"(r1), "=r"(r2), "=r"(r3) : "r"(addr));
}
__device__ __forceinline__ void cp16(uint32_t smaddr, const void* g) {
    asm volatile("cp.async.cg.shared.global [%0], [%1], 16;" :: "r"(smaddr), "l"(g));
}
#define CP_COMMIT() asm volatile("cp.async.commit_group;" ::: "memory")
#define CP_WAIT1()  asm volatile("cp.async.wait_group 1;" ::: "memory")

// ============================================================
// fused: dinv[i] = rsqrt(rowsum |L_i|)  AND  g_Lh = fp16(L)
// ============================================================
__global__ void dinv_conv_kernel(const float* __restrict__ L0,
                                 const float* __restrict__ L1,
                                 const float* __restrict__ L2) {
    int grow = blockIdx.x;
    const float* L; int N; int lr; size_t lbfOff;
    if (grow < NR0)             { L = L0; N = NR0; lr = grow;             lbfOff = LBF_OFF0; }
    else if (grow < NR0 + NR1)  { L = L1; N = NR1; lr = grow - NR0;       lbfOff = LBF_OFF1; }
    else                        { L = L2; N = NR2; lr = grow - NR0 - NR1; lbfOff = LBF_OFF2; }

    const float4* row = (const float4*)(L + (size_t)lr * N);
    uint2* rowOut = (uint2*)(g_Lh + lbfOff + (size_t)lr * N);
    int n4 = N >> 2;
    float s = 0.f;
    for (int j = threadIdx.x; j < n4; j += blockDim.x) {
        float4 v = row[j];
        s += fabsf(v.x) + fabsf(v.y) + fabsf(v.z) + fabsf(v.w);
        rowOut[j] = make_uint2(pack_f16(v.x, v.y), pack_f16(v.z, v.w));
    }
    __shared__ float red[4];
    for (int o = 16; o > 0; o >>= 1) s += __shfl_down_sync(0xffffffffu, s, o);
    if ((threadIdx.x & 31) == 0) red[threadIdx.x >> 5] = s;
    __syncthreads();
    if (threadIdx.x == 0) {
        float d = red[0] + red[1] + red[2] + red[3];
        g_dinv[grow] = (d != 0.f) ? rsqrtf(d) : 0.f;
    }
}

// ============================================================
// zero the two layer-output accumulators (atomicAdd targets)
// ============================================================
__global__ void zero_x_kernel() {
    int i = blockIdx.x * blockDim.x + threadIdx.x;
    float4 z = make_float4(0.f, 0.f, 0.f, 0.f);
    ((float4*)g_xA)[i] = z;
    ((float4*)g_xB)[i] = z;
}

// ============================================================
// z = dinv .* (relu?(x) @ W[layer]); emit fp16 transposed [C][NT]
// 32 rows/block, 128 thr (16x8 grid, 4x4 reg tile). relu applied on
// load for layer 1 (gemm epilogue is linear / no relu).
// ============================================================
#define XSP 68   // xs row pitch in floats
#define ZSP 72   // zs row pitch in halves

__global__ __launch_bounds__(128) void xw_kernel(
    const float* __restrict__ x0, const float* __restrict__ x1,
    const float* __restrict__ x2,
    const float* __restrict__ W0, const float* __restrict__ W1,
    const float* __restrict__ W2, int layer)
{
    __shared__ __align__(16) char sbuf[16384 + 32 * XSP * 4];   // 25088 B
    float* Ws = (float*)sbuf;                   // [64][64]
    float* xs = (float*)(sbuf + 16384);         // [32][XSP]

    int growBase = blockIdx.x * 32;
    const float* W; const float* xsrc;
    if (growBase < NR0) {
        W = W0;
        xsrc = layer ? (g_xA + (size_t)growBase * C) : (x0 + (size_t)growBase * C);
    } else if (growBase < NR0 + NR1) {
        W = W1;
        xsrc = layer ? (g_xA + (size_t)growBase * C) : (x1 + (size_t)(growBase - NR0) * C);
    } else {
        W = W2;
        xsrc = layer ? (g_xA + (size_t)growBase * C) : (x2 + (size_t)(growBase - NR0 - NR1) * C);
    }
    W += layer * C * C;

    int tid = threadIdx.x;
    for (int i = tid; i < C * C; i += 128) Ws[i] = W[i];
    // xs: 32 rows x 16 float4 = 512 float4, 4 per thread; relu for layer 1
    for (int i = tid; i < 32 * 16; i += 128) {
        int row = i >> 4, q = i & 15;
        float4 v = *(const float4*)(xsrc + row * C + q * 4);
        if (layer) {
            v.x = fmaxf(v.x, 0.f); v.y = fmaxf(v.y, 0.f);
            v.z = fmaxf(v.z, 0.f); v.w = fmaxf(v.w, 0.f);
        }
        *(float4*)&xs[row * XSP + q * 4] = v;
    }
    __syncthreads();

    int tx = tid & 15, ty = tid >> 4;           // 16x8 thread grid; 4x4 tile each
    const float4* Ws4 = (const float4*)Ws;

    float acc[4][4];
    #pragma unroll
    for (int i = 0; i < 4; i++)
        #pragma unroll
        for (int j = 0; j < 4; j++) acc[i][j] = 0.f;

    #pragma unroll 8
    for (int k = 0; k < C; k++) {
        float4 w = Ws4[k * 16 + tx];
        #pragma unroll
        for (int i = 0; i < 4; i++) {
            float a = xs[(ty * 4 + i) * XSP + k];
            acc[i][0] += a * w.x;
            acc[i][1] += a * w.y;
            acc[i][2] += a * w.z;
            acc[i][3] += a * w.w;
        }
    }
    __syncthreads();   // xs/Ws reads done; sbuf may be overwritten

    // scale by dinv, convert fp16, stage into overlaid zs
    uint16_t* zs = (uint16_t*)sbuf;             // [32][ZSP] halves
    #pragma unroll
    for (int i = 0; i < 4; i++) {
        int row = ty * 4 + i;
        float dv = g_dinv[growBase + row];
        uint2 p;
        p.x = pack_f16(acc[i][0] * dv, acc[i][1] * dv);
        p.y = pack_f16(acc[i][2] * dv, acc[i][3] * dv);
        *(uint2*)&zs[row * ZSP + tx * 4] = p;
    }
    __syncthreads();

    // transposed write: thread -> channel c2, 16 consecutive rows (2 x uint4)
    int c2 = tid >> 1, seg = tid & 1;
    size_t base = (size_t)c2 * NT + growBase + seg * 16;
    uint16_t hv[16];
    #pragma unroll
    for (int j = 0; j < 16; j++) hv[j] = zs[(seg * 16 + j) * ZSP + c2];
    *(uint4*)&g_zh[base]     = *(uint4*)hv;
    *(uint4*)&g_zh[base + 8] = *(uint4*)(hv + 8);
}

// ============================================================
// cp.async fp16 GEMM, uniform split-K tiles:
//   dst += dinv .* (L[:, kslice] @ z[kslice])   (atomicAdd; no relu)
// BM=64, BN=64, BK=64, K-slice = 2048 (nc = 32 chunks for every CTA).
// 768 uniform CTAs, 3-stage pipeline, 3 CTAs/SM (occ 48%).
// ============================================================
#define SA 72   // smem row pitch in halves (64 data + 8 pad); 144B
#define AH_OFF 0
#define BH_OFF (64 * SA)
#define STAGE_HALVES (2 * 64 * SA)           // 9216 halves = 18432 B
#define STAGE_BYTES  (STAGE_HALVES * 2)
#define NSTAGE 3
#define GEMM_SMEM (NSTAGE * STAGE_BYTES)     // 55296 B
#define KSLICE 2048
#define NCHUNK (KSLICE / 64)                 // 32

__global__ __launch_bounds__(256, 3) void gemm_mma(int layer)
{
    extern __shared__ __align__(16) uint16_t sm[];

    int bx = blockIdx.x;
    int N, lrowBase, growBase, kBase; size_t lbfOff;
    if (bx < 512) {
        N = NR1; int mt = bx >> 2; lrowBase = mt * 64; growBase = NR0 + lrowBase;
        kBase = (bx & 3) * KSLICE; lbfOff = LBF_OFF1;
    } else if (bx < 640) {
        int t = bx - 512;
        N = NR0; lrowBase = (t >> 1) * 64; growBase = lrowBase;
        kBase = (t & 1) * KSLICE; lbfOff = LBF_OFF0;
    } else {
        int t = bx - 640;
        N = NR2; lrowBase = (t >> 1) * 64; growBase = NR0 + NR1 + lrowBase;
        kBase = (t & 1) * KSLICE; lbfOff = LBF_OFF2;
    }
    int zOff = growBase - lrowBase;
    float* dst = layer ? g_xB : g_xA;

    int tid = threadIdx.x;
    int wid = tid >> 5, lane = tid & 31;
    int g = lane >> 2, tg = lane & 3;
    int wm = wid >> 2, wn = wid & 3;     // 2m x 4n warp grid, tile m32n16

    uint32_t smBase = (uint32_t)__cvta_generic_to_shared(sm);

    // ---- ldmatrix lane byte offsets (within stage; +ks*32 bytes per k16 step) ----
    uint32_t aBase[2];
    #pragma unroll
    for (int mt = 0; mt < 2; mt++) {
        int row = wm * 32 + mt * 16 + (lane & 15);
        int col = (lane & 16) ? 8 : 0;
        aBase[mt] = 2u * (AH_OFF + row * SA + col);
    }
    uint32_t bBase;
    {
        int row = wn * 16 + (lane & 7) + ((lane & 16) >> 1);
        int col = (lane & 8) ? 8 : 0;
        bBase = 2u * (BH_OFF + row * SA + col);
    }

    // ---- cp.async loader setup (per chunk: A 8KB + B 8KB; 4 x 16B/thread) ----
    const uint16_t* aSrc[2]; uint32_t aDst[2];
    #pragma unroll
    for (int q = 0; q < 2; q++) {
        int idx = q * 256 + tid;
        int aRow = idx >> 3, aSeg = idx & 7;
        aSrc[q] = g_Lh + lbfOff + (size_t)(lrowBase + aRow) * N + kBase + aSeg * 8;
        aDst[q] = 2u * (AH_OFF + aRow * SA + aSeg * 8);
    }
    const uint16_t* bSrc[2]; uint32_t bDst[2];
    #pragma unroll
    for (int q = 0; q < 2; q++) {
        int idx = q * 256 + tid;
        int bRow = idx >> 3, bSeg = idx & 7;
        bSrc[q] = g_zh + (size_t)bRow * NT + zOff + kBase + bSeg * 8;
        bDst[q] = 2u * (BH_OFF + bRow * SA + bSeg * 8);
    }

    float acc[2][2][4];
    #pragma unroll
    for (int mt = 0; mt < 2; mt++)
        #pragma unroll
        for (int nt = 0; nt < 2; nt++)
            #pragma unroll
            for (int i = 0; i < 4; i++) acc[mt][nt][i] = 0.f;

    int sIssue = 0, sComp = 0;

    // ---- prologue: issue chunks 0,1 ----
    #pragma unroll
    for (int p = 0; p < 2; p++) {
        uint32_t st = smBase + (uint32_t)sIssue * STAGE_BYTES;
        int k0 = p * 64;
        #pragma unroll
        for (int q = 0; q < 2; q++) cp16(st + aDst[q], aSrc[q] + k0);
        #pragma unroll
        for (int q = 0; q < 2; q++) cp16(st + bDst[q], bSrc[q] + k0);
        CP_COMMIT();
        if (++sIssue == NSTAGE) sIssue = 0;
    }

    // ---- mainloop ----
    for (int cI = 0; cI < NCHUNK; cI++) {
        CP_WAIT1();
        __syncthreads();

        if (cI + 2 < NCHUNK) {
            uint32_t st = smBase + (uint32_t)sIssue * STAGE_BYTES;
            int k0 = (cI + 2) * 64;
            #pragma unroll
            for (int q = 0; q < 2; q++) cp16(st + aDst[q], aSrc[q] + k0);
            #pragma unroll
            for (int q = 0; q < 2; q++) cp16(st + bDst[q], bSrc[q] + k0);
        }
        CP_COMMIT();   // unconditional: keeps wait_group accounting correct at tail
        if (++sIssue == NSTAGE) sIssue = 0;

        uint32_t stage = smBase + (uint32_t)sComp * STAGE_BYTES;
        if (++sComp == NSTAGE) sComp = 0;
        #pragma unroll
        for (int ks = 0; ks < 4; ks++) {
            uint32_t ah[2][4];
            #pragma unroll
            for (int mt = 0; mt < 2; mt++)
                ldsm_x4(ah[mt][0], ah[mt][1], ah[mt][2], ah[mt][3],
                        stage + aBase[mt] + ks * 32);
            uint32_t bv[2][2];
            ldsm_x4(bv[0][0], bv[0][1], bv[1][0], bv[1][1], stage + bBase + ks * 32);
            #pragma unroll
            for (int mt = 0; mt < 2; mt++)
                #pragma unroll
                for (int nt = 0; nt < 2; nt++)
                    mma_f16(acc[mt][nt], ah[mt], bv[nt]);
        }
    }

    // ---- epilogue: dinv row-scale, atomicAdd partial (no relu) ----
    #pragma unroll
    for (int mt = 0; mt < 2; mt++) {
        int row0 = wm * 32 + mt * 16 + g;
        float dv0 = g_dinv[growBase + row0];
        float dv1 = g_dinv[growBase + row0 + 8];
        #pragma unroll
        for (int nt = 0; nt < 2; nt++) {
            int col = wn * 16 + nt * 8 + tg * 2;
            float* c = acc[mt][nt];
            float* p0 = &dst[(size_t)(growBase + row0) * C + col];
            float* p1 = &dst[(size_t)(growBase + row0 + 8) * C + col];
            atomicAdd(p0,     c[0] * dv0);
            atomicAdd(p0 + 1, c[1] * dv0);
            atomicAdd(p1,     c[2] * dv1);
            atomicAdd(p1 + 1, c[3] * dv1);
        }
    }
}

// ============================================================
// readout (relu applied on read of final layer output)
// ============================================================
__global__ void zero_pooled_kernel() {
    int i = blockIdx.x * blockDim.x + threadIdx.x;
    if (i < 3 * NB * C) g_pooled[i] = 0.f;
}

__global__ void pool_kernel(const int* __restrict__ bel0,
                            const int* __restrict__ bel1,
                            const int* __restrict__ bel2) {
    int grow = blockIdx.x;
    int rank, lr;
    if (grow < NR0)            { rank = 0; lr = grow; }
    else if (grow < NR0 + NR1) { rank = 1; lr = grow - NR0; }
    else                       { rank = 2; lr = grow - NR0 - NR1; }
    const int* bel = (rank == 0) ? bel0 : (rank == 1 ? bel1 : bel2);
    int b = bel[lr];
    float v = fmaxf(g_xB[(size_t)grow * C + threadIdx.x], 0.f);
    atomicAdd(&g_pooled[rank * NB * C + b * C + threadIdx.x], v);
}

__global__ void out_kernel(const float* __restrict__ Wr0, const float* __restrict__ br0,
                           const float* __restrict__ Wr1, const float* __restrict__ br1,
                           const float* __restrict__ Wr2, const float* __restrict__ br2,
                           float* __restrict__ out) {
    int b = blockIdx.x;
    int o = threadIdx.x;
    float acc = br0[o] + br1[o] + br2[o];
    const float* Wrs[3] = {Wr0, Wr1, Wr2};
    #pragma unroll
    for (int r = 0; r < 3; r++) {
        const float* Wr = Wrs[r];
        const float* p  = &g_pooled[r * NB * C + b * C];
        #pragma unroll 8
        for (int c = 0; c < C; c++) acc += p[c] * Wr[c * OUTC + o];
    }
    out[b * OUTC + o] = acc;
}

// ============================================================
extern "C" void kernel_launch(void* const* d_in, const int* in_sizes, int n_in,
                              void* d_out, int out_size) {
    const float* x0  = (const float*)d_in[0];
    const float* x1  = (const float*)d_in[1];
    const float* x2  = (const float*)d_in[2];
    const float* L0  = (const float*)d_in[3];
    const float* L1  = (const float*)d_in[4];
    const float* L2  = (const float*)d_in[5];
    const int*   bel0 = (const int*)d_in[6];
    const int*   bel1 = (const int*)d_in[7];
    const int*   bel2 = (const int*)d_in[8];
    const float* W0  = (const float*)d_in[9];
    const float* W1  = (const float*)d_in[10];
    const float* W2  = (const float*)d_in[11];
    const float* Wr0 = (const float*)d_in[12];
    const float* br0 = (const float*)d_in[13];
    const float* Wr1 = (const float*)d_in[14];
    const float* br1 = (const float*)d_in[15];
    const float* Wr2 = (const float*)d_in[16];
    const float* br2 = (const float*)d_in[17];

    cudaFuncSetAttribute(gemm_mma, cudaFuncAttributeMaxDynamicSharedMemorySize, GEMM_SMEM);

    dinv_conv_kernel<<<NT, 128>>>(L0, L1, L2);
    zero_x_kernel<<<(NT * C / 4) / 256, 256>>>();   // zero g_xA + g_xB

    for (int layer = 0; layer < 2; layer++) {
        xw_kernel<<<NT / 32, 128>>>(x0, x1, x2, W0, W1, W2, layer);
        gemm_mma<<<768, 256, GEMM_SMEM>>>(layer);
    }

    zero_pooled_kernel<<<(3 * NB * C + 255) / 256, 256>>>();
    pool_kernel<<<NT, 64>>>(bel0, bel1, bel2);
    out_kernel<<<NB, OUTC>>>(Wr0, br0, Wr1, br1, Wr2, br2, (float*)d_out);
}

// round 14
// speedup vs baseline: 1.0476x; 1.0476x over previous
#include <cuda_runtime.h>
#include <cuda_fp16.h>
#include <cstdint>

#define NR0 4096
#define NR1 8192
#define NR2 4096
#define NT  16384     // NR0+NR1+NR2
#define C   64
#define OUTC 32
#define NB  64

// fp16 copies of the L matrices (written once by dinv_conv_kernel)
#define LBF_OFF0 0
#define LBF_OFF1 ((size_t)NR0 * NR0)
#define LBF_OFF2 (LBF_OFF1 + (size_t)NR1 * NR1)
#define LBF_TOTAL (LBF_OFF2 + (size_t)NR2 * NR2)

// ---- scratch (device globals; no allocation allowed) ----
__device__ float    g_dinv[NT];
__device__ uint16_t g_Lh[LBF_TOTAL];    // fp16 L
__device__ uint16_t g_zh[C * NT];       // fp16 z^T [C][NT] (K-major B operand)
__device__ float    g_xA[NT * C];       // layer outputs (pre-relu; consumers apply relu)
__device__ float    g_xB[NT * C];
__device__ float    g_pooled[3 * NB * C];

// ============================================================
// helpers
// ============================================================
__device__ __forceinline__ uint32_t pack_f16(float lo, float hi) {
    __half2 h = __floats2half2_rn(lo, hi);   // lo -> low 16 bits
    return *(uint32_t*)&h;
}
__device__ __forceinline__ void mma_f16(float* c, const uint32_t* a, const uint32_t* b) {
    asm volatile("mma.sync.aligned.m16n8k16.row.col.f32.f16.f16.f32 "
        "{%0,%1,%2,%3}, {%4,%5,%6,%7}, {%8,%9}, {%0,%1,%2,%3};"
        : "+f"(c[0]), "+f"(c[1]), "+f"(c[2]), "+f"(c[3])
        : "r"(a[0]), "r"(a[1]), "r"(a[2]), "r"(a[3]), "r"(b[0]), "r"(b[1]));
}
__device__ __forceinline__ void ldsm_x4(uint32_t& r0, uint32_t& r1, uint32_t& r2,
                                        uint32_t& r3, uint32_t addr) {
    asm volatile("ldmatrix.sync.aligned.m8n8.x4.shared.b16 {%0,%1,%2,%3}, [%4];"
                 : "=r"(r0), "=r"(r1), "=r"(r2), "=r"(r3) : "r"(addr));
}
__device__ __forceinline__ void cp16(uint32_t smaddr, const void* g) {
    asm volatile("cp.async.cg.shared.global [%0], [%1], 16;" :: "r"(smaddr), "l"(g));
}
#define CP_COMMIT() asm volatile("cp.async.commit_group;" ::: "memory")
#define CP_WAIT1()  asm volatile("cp.async.wait_group 1;" ::: "memory")

// ============================================================
// fused: dinv[i] = rsqrt(rowsum |L_i|)  AND  g_Lh = fp16(L)
// ============================================================
__global__ void dinv_conv_kernel(const float* __restrict__ L0,
                                 const float* __restrict__ L1,
                                 const float* __restrict__ L2) {
    int grow = blockIdx.x;
    const float* L; int N; int lr; size_t lbfOff;
    if (grow < NR0)             { L = L0; N = NR0; lr = grow;             lbfOff = LBF_OFF0; }
    else if (grow < NR0 + NR1)  { L = L1; N = NR1; lr = grow - NR0;       lbfOff = LBF_OFF1; }
    else                        { L = L2; N = NR2; lr = grow - NR0 - NR1; lbfOff = LBF_OFF2; }

    const float4* row = (const float4*)(L + (size_t)lr * N);
    uint2* rowOut = (uint2*)(g_Lh + lbfOff + (size_t)lr * N);
    int n4 = N >> 2;
    float s = 0.f;
    for (int j = threadIdx.x; j < n4; j += blockDim.x) {
        float4 v = row[j];
        s += fabsf(v.x) + fabsf(v.y) + fabsf(v.z) + fabsf(v.w);
        rowOut[j] = make_uint2(pack_f16(v.x, v.y), pack_f16(v.z, v.w));
    }
    __shared__ float red[4];
    for (int o = 16; o > 0; o >>= 1) s += __shfl_down_sync(0xffffffffu, s, o);
    if ((threadIdx.x & 31) == 0) red[threadIdx.x >> 5] = s;
    __syncthreads();
    if (threadIdx.x == 0) {
        float d = red[0] + red[1] + red[2] + red[3];
        g_dinv[grow] = (d != 0.f) ? rsqrtf(d) : 0.f;
    }
}

// ============================================================
// zero the two layer-output accumulators (atomicAdd targets)
// ============================================================
__global__ void zero_x_kernel() {
    int i = blockIdx.x * blockDim.x + threadIdx.x;
    float4 z = make_float4(0.f, 0.f, 0.f, 0.f);
    ((float4*)g_xA)[i] = z;
    ((float4*)g_xB)[i] = z;
}

// ============================================================
// z = dinv .* (relu?(x) @ W[layer]); emit fp16 transposed [C][NT]
// 32 rows/block, 128 thr (16x8 grid, 4x4 reg tile). relu applied on
// load for layer 1 (gemm epilogue is linear / no relu).
// ============================================================
#define XSP 68   // xs row pitch in floats
#define ZSP 72   // zs row pitch in halves

__global__ __launch_bounds__(128) void xw_kernel(
    const float* __restrict__ x0, const float* __restrict__ x1,
    const float* __restrict__ x2,
    const float* __restrict__ W0, const float* __restrict__ W1,
    const float* __restrict__ W2, int layer)
{
    __shared__ __align__(16) char sbuf[16384 + 32 * XSP * 4];   // 25088 B
    float* Ws = (float*)sbuf;                   // [64][64]
    float* xs = (float*)(sbuf + 16384);         // [32][XSP]

    int growBase = blockIdx.x * 32;
    const float* W; const float* xsrc;
    if (growBase < NR0) {
        W = W0;
        xsrc = layer ? (g_xA + (size_t)growBase * C) : (x0 + (size_t)growBase * C);
    } else if (growBase < NR0 + NR1) {
        W = W1;
        xsrc = layer ? (g_xA + (size_t)growBase * C) : (x1 + (size_t)(growBase - NR0) * C);
    } else {
        W = W2;
        xsrc = layer ? (g_xA + (size_t)growBase * C) : (x2 + (size_t)(growBase - NR0 - NR1) * C);
    }
    W += layer * C * C;

    int tid = threadIdx.x;
    for (int i = tid; i < C * C; i += 128) Ws[i] = W[i];
    for (int i = tid; i < 32 * 16; i += 128) {
        int row = i >> 4, q = i & 15;
        float4 v = *(const float4*)(xsrc + row * C + q * 4);
        if (layer) {
            v.x = fmaxf(v.x, 0.f); v.y = fmaxf(v.y, 0.f);
            v.z = fmaxf(v.z, 0.f); v.w = fmaxf(v.w, 0.f);
        }
        *(float4*)&xs[row * XSP + q * 4] = v;
    }
    __syncthreads();

    int tx = tid & 15, ty = tid >> 4;           // 16x8 thread grid; 4x4 tile each
    const float4* Ws4 = (const float4*)Ws;

    float acc[4][4];
    #pragma unroll
    for (int i = 0; i < 4; i++)
        #pragma unroll
        for (int j = 0; j < 4; j++) acc[i][j] = 0.f;

    #pragma unroll 8
    for (int k = 0; k < C; k++) {
        float4 w = Ws4[k * 16 + tx];
        #pragma unroll
        for (int i = 0; i < 4; i++) {
            float a = xs[(ty * 4 + i) * XSP + k];
            acc[i][0] += a * w.x;
            acc[i][1] += a * w.y;
            acc[i][2] += a * w.z;
            acc[i][3] += a * w.w;
        }
    }
    __syncthreads();   // xs/Ws reads done; sbuf may be overwritten

    uint16_t* zs = (uint16_t*)sbuf;             // [32][ZSP] halves
    #pragma unroll
    for (int i = 0; i < 4; i++) {
        int row = ty * 4 + i;
        float dv = g_dinv[growBase + row];
        uint2 p;
        p.x = pack_f16(acc[i][0] * dv, acc[i][1] * dv);
        p.y = pack_f16(acc[i][2] * dv, acc[i][3] * dv);
        *(uint2*)&zs[row * ZSP + tx * 4] = p;
    }
    __syncthreads();

    int c2 = tid >> 1, seg = tid & 1;
    size_t base = (size_t)c2 * NT + growBase + seg * 16;
    uint16_t hv[16];
    #pragma unroll
    for (int j = 0; j < 16; j++) hv[j] = zs[(seg * 16 + j) * ZSP + c2];
    *(uint4*)&g_zh[base]     = *(uint4*)hv;
    *(uint4*)&g_zh[base + 8] = *(uint4*)(hv + 8);
}

// ============================================================
// cp.async fp16 GEMM, uniform split-K tiles:
//   dst += dinv .* (L[:, kslice] @ z[kslice])   (atomicAdd; no relu)
// BM=128, BN=64, BK=64, K-slice = 1024 (nc = 16 for every CTA).
// 8 warps = 4m x 2n, warp tile m32n32 (8 independent MMA chains).
// 768 uniform CTAs, 3-stage pipeline, 2 CTAs/SM.
// ============================================================
#define SA 72   // smem row pitch in halves (64 data + 8 pad); 144B
#define AH_OFF 0
#define BH_OFF (128 * SA)
#define STAGE_HALVES ((128 + 64) * SA)       // 13824 halves = 27648 B
#define STAGE_BYTES  (STAGE_HALVES * 2)
#define NSTAGE 3
#define GEMM_SMEM (NSTAGE * STAGE_BYTES)     // 82944 B
#define KSLICE 1024
#define NCHUNK (KSLICE / 64)                 // 16

__global__ __launch_bounds__(256, 2) void gemm_mma(int layer)
{
    extern __shared__ __align__(16) uint16_t sm[];

    int bx = blockIdx.x;
    int N, lrowBase, growBase, kBase; size_t lbfOff;
    if (bx < 512) {
        // rank1: 64 m-tiles x 8 k-slices
        N = NR1; lrowBase = (bx >> 3) * 128; growBase = NR0 + lrowBase;
        kBase = (bx & 7) * KSLICE; lbfOff = LBF_OFF1;
    } else if (bx < 640) {
        // rank0: 32 m-tiles x 4 k-slices
        int t = bx - 512;
        N = NR0; lrowBase = (t >> 2) * 128; growBase = lrowBase;
        kBase = (t & 3) * KSLICE; lbfOff = LBF_OFF0;
    } else {
        int t = bx - 640;
        N = NR2; lrowBase = (t >> 2) * 128; growBase = NR0 + NR1 + lrowBase;
        kBase = (t & 3) * KSLICE; lbfOff = LBF_OFF2;
    }
    int zOff = growBase - lrowBase;
    float* dst = layer ? g_xB : g_xA;

    int tid = threadIdx.x;
    int wid = tid >> 5, lane = tid & 31;
    int g = lane >> 2, tg = lane & 3;
    int wm = wid >> 1, wn = wid & 1;     // 4m x 2n warp grid, tile m32n32

    uint32_t smBase = (uint32_t)__cvta_generic_to_shared(sm);

    // ---- ldmatrix lane byte offsets (within stage; +ks*32 bytes per k16 step) ----
    uint32_t aBase[2];
    #pragma unroll
    for (int mt = 0; mt < 2; mt++) {
        int row = wm * 32 + mt * 16 + (lane & 15);
        int col = (lane & 16) ? 8 : 0;
        aBase[mt] = 2u * (AH_OFF + row * SA + col);
    }
    uint32_t bBase[2];
    #pragma unroll
    for (int p = 0; p < 2; p++) {
        int row = wn * 32 + p * 16 + (lane & 7) + ((lane & 16) >> 1);
        int col = (lane & 8) ? 8 : 0;
        bBase[p] = 2u * (BH_OFF + row * SA + col);
    }

    // ---- cp.async loader setup (per chunk: A 16KB + B 8KB; 6 x 16B/thread) ----
    const uint16_t* aSrc[4]; uint32_t aDst[4];
    #pragma unroll
    for (int q = 0; q < 4; q++) {
        int idx = q * 256 + tid;
        int aRow = idx >> 3, aSeg = idx & 7;
        aSrc[q] = g_Lh + lbfOff + (size_t)(lrowBase + aRow) * N + kBase + aSeg * 8;
        aDst[q] = 2u * (AH_OFF + aRow * SA + aSeg * 8);
    }
    const uint16_t* bSrc[2]; uint32_t bDst[2];
    #pragma unroll
    for (int q = 0; q < 2; q++) {
        int idx = q * 256 + tid;
        int bRow = idx >> 3, bSeg = idx & 7;
        bSrc[q] = g_zh + (size_t)bRow * NT + zOff + kBase + bSeg * 8;
        bDst[q] = 2u * (BH_OFF + bRow * SA + bSeg * 8);
    }

    float acc[2][4][4];
    #pragma unroll
    for (int mt = 0; mt < 2; mt++)
        #pragma unroll
        for (int nt = 0; nt < 4; nt++)
            #pragma unroll
            for (int i = 0; i < 4; i++) acc[mt][nt][i] = 0.f;

    int sIssue = 0, sComp = 0;

    // ---- prologue: issue chunks 0,1 ----
    #pragma unroll
    for (int p = 0; p < 2; p++) {
        uint32_t st = smBase + (uint32_t)sIssue * STAGE_BYTES;
        int k0 = p * 64;
        #pragma unroll
        for (int q = 0; q < 4; q++) cp16(st + aDst[q], aSrc[q] + k0);
        #pragma unroll
        for (int q = 0; q < 2; q++) cp16(st + bDst[q], bSrc[q] + k0);
        CP_COMMIT();
        if (++sIssue == NSTAGE) sIssue = 0;
    }

    // ---- mainloop ----
    for (int cI = 0; cI < NCHUNK; cI++) {
        CP_WAIT1();
        __syncthreads();

        if (cI + 2 < NCHUNK) {
            uint32_t st = smBase + (uint32_t)sIssue * STAGE_BYTES;
            int k0 = (cI + 2) * 64;
            #pragma unroll
            for (int q = 0; q < 4; q++) cp16(st + aDst[q], aSrc[q] + k0);
            #pragma unroll
            for (int q = 0; q < 2; q++) cp16(st + bDst[q], bSrc[q] + k0);
        }
        CP_COMMIT();   // unconditional: keeps wait_group accounting correct at tail
        if (++sIssue == NSTAGE) sIssue = 0;

        uint32_t stage = smBase + (uint32_t)sComp * STAGE_BYTES;
        if (++sComp == NSTAGE) sComp = 0;
        #pragma unroll
        for (int ks = 0; ks < 4; ks++) {
            uint32_t ah[2][4];
            #pragma unroll
            for (int mt = 0; mt < 2; mt++)
                ldsm_x4(ah[mt][0], ah[mt][1], ah[mt][2], ah[mt][3],
                        stage + aBase[mt] + ks * 32);
            uint32_t bv[4][2];
            #pragma unroll
            for (int p = 0; p < 2; p++)
                ldsm_x4(bv[p * 2][0], bv[p * 2][1], bv[p * 2 + 1][0], bv[p * 2 + 1][1],
                        stage + bBase[p] + ks * 32);
            #pragma unroll
            for (int mt = 0; mt < 2; mt++)
                #pragma unroll
                for (int nt = 0; nt < 4; nt++)
                    mma_f16(acc[mt][nt], ah[mt], bv[nt]);
        }
    }

    // ---- epilogue: dinv row-scale, atomicAdd partial (no relu) ----
    #pragma unroll
    for (int mt = 0; mt < 2; mt++) {
        int row0 = wm * 32 + mt * 16 + g;
        float dv0 = g_dinv[growBase + row0];
        float dv1 = g_dinv[growBase + row0 + 8];
        #pragma unroll
        for (int nt = 0; nt < 4; nt++) {
            int col = wn * 32 + nt * 8 + tg * 2;
            float* c = acc[mt][nt];
            float* p0 = &dst[(size_t)(growBase + row0) * C + col];
            float* p1 = &dst[(size_t)(growBase + row0 + 8) * C + col];
            atomicAdd(p0,     c[0] * dv0);
            atomicAdd(p0 + 1, c[1] * dv0);
            atomicAdd(p1,     c[2] * dv1);
            atomicAdd(p1 + 1, c[3] * dv1);
        }
    }
}

// ============================================================
// readout (relu applied on read of final layer output)
// ============================================================
__global__ void zero_pooled_kernel() {
    int i = blockIdx.x * blockDim.x + threadIdx.x;
    if (i < 3 * NB * C) g_pooled[i] = 0.f;
}

__global__ void pool_kernel(const int* __restrict__ bel0,
                            const int* __restrict__ bel1,
                            const int* __restrict__ bel2) {
    int grow = blockIdx.x;
    int rank, lr;
    if (grow < NR0)            { rank = 0; lr = grow; }
    else if (grow < NR0 + NR1) { rank = 1; lr = grow - NR0; }
    else                       { rank = 2; lr = grow - NR0 - NR1; }
    const int* bel = (rank == 0) ? bel0 : (rank == 1 ? bel1 : bel2);
    int b = bel[lr];
    float v = fmaxf(g_xB[(size_t)grow * C + threadIdx.x], 0.f);
    atomicAdd(&g_pooled[rank * NB * C + b * C + threadIdx.x], v);
}

__global__ void out_kernel(const float* __restrict__ Wr0, const float* __restrict__ br0,
                           const float* __restrict__ Wr1, const float* __restrict__ br1,
                           const float* __restrict__ Wr2, const float* __restrict__ br2,
                           float* __restrict__ out) {
    int b = blockIdx.x;
    int o = threadIdx.x;
    float acc = br0[o] + br1[o] + br2[o];
    const float* Wrs[3] = {Wr0, Wr1, Wr2};
    #pragma unroll
    for (int r = 0; r < 3; r++) {
        const float* Wr = Wrs[r];
        const float* p  = &g_pooled[r * NB * C + b * C];
        #pragma unroll 8
        for (int c = 0; c < C; c++) acc += p[c] * Wr[c * OUTC + o];
    }
    out[b * OUTC + o] = acc;
}

// ============================================================
extern "C" void kernel_launch(void* const* d_in, const int* in_sizes, int n_in,
                              void* d_out, int out_size) {
    const float* x0  = (const float*)d_in[0];
    const float* x1  = (const float*)d_in[1];
    const float* x2  = (const float*)d_in[2];
    const float* L0  = (const float*)d_in[3];
    const float* L1  = (const float*)d_in[4];
    const float* L2  = (const float*)d_in[5];
    const int*   bel0 = (const int*)d_in[6];
    const int*   bel1 = (const int*)d_in[7];
    const int*   bel2 = (const int*)d_in[8];
    const float* W0  = (const float*)d_in[9];
    const float* W1  = (const float*)d_in[10];
    const float* W2  = (const float*)d_in[11];
    const float* Wr0 = (const float*)d_in[12];
    const float* br0 = (const float*)d_in[13];
    const float* Wr1 = (const float*)d_in[14];
    const float* br1 = (const float*)d_in[15];
    const float* Wr2 = (const float*)d_in[16];
    const float* br2 = (const float*)d_in[17];

    cudaFuncSetAttribute(gemm_mma, cudaFuncAttributeMaxDynamicSharedMemorySize, GEMM_SMEM);

    dinv_conv_kernel<<<NT, 128>>>(L0, L1, L2);
    zero_x_kernel<<<(NT * C / 4) / 256, 256>>>();   // zero g_xA + g_xB

    for (int layer = 0; layer < 2; layer++) {
        xw_kernel<<<NT / 32, 128>>>(x0, x1, x2, W0, W1, W2, layer);
        gemm_mma<<<768, 256, GEMM_SMEM>>>(layer);
    }

    zero_pooled_kernel<<<(3 * NB * C + 255) / 256, 256>>>();
    pool_kernel<<<NT, 64>>>(bel0, bel1, bel2);
    out_kernel<<<NB, OUTC>>>(Wr0, br0, Wr1, br1, Wr2, br2, (float*)d_out);
}

// round 15
// speedup vs baseline: 1.0605x; 1.0123x over previous
#include <cuda_runtime.h>
#include <cuda_fp16.h>
#include <cstdint>

#define NR0 4096
#define NR1 8192
#define NR2 4096
#define NT  16384     // NR0+NR1+NR2
#define C   64
#define OUTC 32
#define NB  64

// fp16 copies of the L matrices (written once by dinv_conv_kernel)
#define LBF_OFF0 0
#define LBF_OFF1 ((size_t)NR0 * NR0)
#define LBF_OFF2 (LBF_OFF1 + (size_t)NR1 * NR1)
#define LBF_TOTAL (LBF_OFF2 + (size_t)NR2 * NR2)

// ---- scratch (device globals; no allocation allowed) ----
__device__ float    g_dinv[NT];
__device__ uint16_t g_Lh[LBF_TOTAL];    // fp16 L
__device__ uint16_t g_zh[C * NT];       // fp16 z^T [C][NT] (K-major B operand)
__device__ float    g_xA[NT * C];       // layer outputs (pre-relu; consumers apply relu)
__device__ float    g_xB[NT * C];
__device__ float    g_pooled[3 * NB * C];

// ============================================================
// helpers
// ============================================================
__device__ __forceinline__ uint32_t pack_f16(float lo, float hi) {
    __half2 h = __floats2half2_rn(lo, hi);   // lo -> low 16 bits
    return *(uint32_t*)&h;
}
__device__ __forceinline__ void mma_f16(float* c, const uint32_t* a, const uint32_t* b) {
    asm volatile("mma.sync.aligned.m16n8k16.row.col.f32.f16.f16.f32 "
        "{%0,%1,%2,%3}, {%4,%5,%6,%7}, {%8,%9}, {%0,%1,%2,%3};"
        : "+f"(c[0]), "+f"(c[1]), "+f"(c[2]), "+f"(c[3])
        : "r"(a[0]), "r"(a[1]), "r"(a[2]), "r"(a[3]), "r"(b[0]), "r"(b[1]));
}
__device__ __forceinline__ void ldsm_x4(uint32_t& r0, uint32_t& r1, uint32_t& r2,
                                        uint32_t& r3, uint32_t addr) {
    asm volatile("ldmatrix.sync.aligned.m8n8.x4.shared.b16 {%0,%1,%2,%3}, [%4];"
                 : "=r"(r0), "=r"(r1), "=r"(r2), "=r"(r3) : "r"(addr));
}
__device__ __forceinline__ void cp16(uint32_t smaddr, const void* g) {
    asm volatile("cp.async.cg.shared.global [%0], [%1], 16;" :: "r"(smaddr), "l"(g));
}
#define CP_COMMIT() asm volatile("cp.async.commit_group;" ::: "memory")
#define CP_WAIT2()  asm volatile("cp.async.wait_group 2;" ::: "memory")

// ============================================================
// fused: dinv[i] = rsqrt(rowsum |L_i|)  AND  g_Lh = fp16(L)
// ============================================================
__global__ void dinv_conv_kernel(const float* __restrict__ L0,
                                 const float* __restrict__ L1,
                                 const float* __restrict__ L2) {
    int grow = blockIdx.x;
    const float* L; int N; int lr; size_t lbfOff;
    if (grow < NR0)             { L = L0; N = NR0; lr = grow;             lbfOff = LBF_OFF0; }
    else if (grow < NR0 + NR1)  { L = L1; N = NR1; lr = grow - NR0;       lbfOff = LBF_OFF1; }
    else                        { L = L2; N = NR2; lr = grow - NR0 - NR1; lbfOff = LBF_OFF2; }

    const float4* row = (const float4*)(L + (size_t)lr * N);
    uint2* rowOut = (uint2*)(g_Lh + lbfOff + (size_t)lr * N);
    int n4 = N >> 2;
    float s = 0.f;
    for (int j = threadIdx.x; j < n4; j += blockDim.x) {
        float4 v = row[j];
        s += fabsf(v.x) + fabsf(v.y) + fabsf(v.z) + fabsf(v.w);
        rowOut[j] = make_uint2(pack_f16(v.x, v.y), pack_f16(v.z, v.w));
    }
    __shared__ float red[4];
    for (int o = 16; o > 0; o >>= 1) s += __shfl_down_sync(0xffffffffu, s, o);
    if ((threadIdx.x & 31) == 0) red[threadIdx.x >> 5] = s;
    __syncthreads();
    if (threadIdx.x == 0) {
        float d = red[0] + red[1] + red[2] + red[3];
        g_dinv[grow] = (d != 0.f) ? rsqrtf(d) : 0.f;
    }
}

// ============================================================
// zero the two layer-output accumulators (atomicAdd targets)
// ============================================================
__global__ void zero_x_kernel() {
    int i = blockIdx.x * blockDim.x + threadIdx.x;
    float4 z = make_float4(0.f, 0.f, 0.f, 0.f);
    ((float4*)g_xA)[i] = z;
    ((float4*)g_xB)[i] = z;
}

// ============================================================
// z = dinv .* (relu?(x) @ W[layer]); emit fp16 transposed [C][NT]
// 32 rows/block, 128 thr (16x8 grid, 4x4 reg tile). relu applied on
// load for layer 1 (gemm epilogue is linear / no relu).
// ============================================================
#define XSP 68   // xs row pitch in floats
#define ZSP 72   // zs row pitch in halves

__global__ __launch_bounds__(128) void xw_kernel(
    const float* __restrict__ x0, const float* __restrict__ x1,
    const float* __restrict__ x2,
    const float* __restrict__ W0, const float* __restrict__ W1,
    const float* __restrict__ W2, int layer)
{
    __shared__ __align__(16) char sbuf[16384 + 32 * XSP * 4];   // 25088 B
    float* Ws = (float*)sbuf;                   // [64][64]
    float* xs = (float*)(sbuf + 16384);         // [32][XSP]

    int growBase = blockIdx.x * 32;
    const float* W; const float* xsrc;
    if (growBase < NR0) {
        W = W0;
        xsrc = layer ? (g_xA + (size_t)growBase * C) : (x0 + (size_t)growBase * C);
    } else if (growBase < NR0 + NR1) {
        W = W1;
        xsrc = layer ? (g_xA + (size_t)growBase * C) : (x1 + (size_t)(growBase - NR0) * C);
    } else {
        W = W2;
        xsrc = layer ? (g_xA + (size_t)growBase * C) : (x2 + (size_t)(growBase - NR0 - NR1) * C);
    }
    W += layer * C * C;

    int tid = threadIdx.x;
    for (int i = tid; i < C * C; i += 128) Ws[i] = W[i];
    for (int i = tid; i < 32 * 16; i += 128) {
        int row = i >> 4, q = i & 15;
        float4 v = *(const float4*)(xsrc + row * C + q * 4);
        if (layer) {
            v.x = fmaxf(v.x, 0.f); v.y = fmaxf(v.y, 0.f);
            v.z = fmaxf(v.z, 0.f); v.w = fmaxf(v.w, 0.f);
        }
        *(float4*)&xs[row * XSP + q * 4] = v;
    }
    __syncthreads();

    int tx = tid & 15, ty = tid >> 4;           // 16x8 thread grid; 4x4 tile each
    const float4* Ws4 = (const float4*)Ws;

    float acc[4][4];
    #pragma unroll
    for (int i = 0; i < 4; i++)
        #pragma unroll
        for (int j = 0; j < 4; j++) acc[i][j] = 0.f;

    #pragma unroll 8
    for (int k = 0; k < C; k++) {
        float4 w = Ws4[k * 16 + tx];
        #pragma unroll
        for (int i = 0; i < 4; i++) {
            float a = xs[(ty * 4 + i) * XSP + k];
            acc[i][0] += a * w.x;
            acc[i][1] += a * w.y;
            acc[i][2] += a * w.z;
            acc[i][3] += a * w.w;
        }
    }
    __syncthreads();   // xs/Ws reads done; sbuf may be overwritten

    uint16_t* zs = (uint16_t*)sbuf;             // [32][ZSP] halves
    #pragma unroll
    for (int i = 0; i < 4; i++) {
        int row = ty * 4 + i;
        float dv = g_dinv[growBase + row];
        uint2 p;
        p.x = pack_f16(acc[i][0] * dv, acc[i][1] * dv);
        p.y = pack_f16(acc[i][2] * dv, acc[i][3] * dv);
        *(uint2*)&zs[row * ZSP + tx * 4] = p;
    }
    __syncthreads();

    int c2 = tid >> 1, seg = tid & 1;
    size_t base = (size_t)c2 * NT + growBase + seg * 16;
    uint16_t hv[16];
    #pragma unroll
    for (int j = 0; j < 16; j++) hv[j] = zs[(seg * 16 + j) * ZSP + c2];
    *(uint4*)&g_zh[base]     = *(uint4*)hv;
    *(uint4*)&g_zh[base + 8] = *(uint4*)(hv + 8);
}

// ============================================================
// cp.async fp16 GEMM, uniform split-K tiles:
//   dst += dinv .* (L[:, kslice] @ z[kslice])   (atomicAdd; no relu)
// BM=128, BN=64, BK=64, K-slice = 1024 (nc = 16 for every CTA).
// 8 warps = 4m x 2n, warp tile m32n32; warp-staggered ks order to
// de-phase LDSM/HMMA bursts. 4-stage pipeline (distance 3), 2 CTAs/SM.
// ============================================================
#define SA 72   // smem row pitch in halves (64 data + 8 pad); 144B
#define AH_OFF 0
#define BH_OFF (128 * SA)
#define STAGE_HALVES ((128 + 64) * SA)       // 13824 halves = 27648 B
#define STAGE_BYTES  (STAGE_HALVES * 2)
#define NSTAGE 4
#define GEMM_SMEM (NSTAGE * STAGE_BYTES)     // 110592 B
#define KSLICE 1024
#define NCHUNK (KSLICE / 64)                 // 16

__global__ __launch_bounds__(256, 2) void gemm_mma(int layer)
{
    extern __shared__ __align__(16) uint16_t sm[];

    int bx = blockIdx.x;
    int N, lrowBase, growBase, kBase; size_t lbfOff;
    if (bx < 512) {
        N = NR1; lrowBase = (bx >> 3) * 128; growBase = NR0 + lrowBase;
        kBase = (bx & 7) * KSLICE; lbfOff = LBF_OFF1;
    } else if (bx < 640) {
        int t = bx - 512;
        N = NR0; lrowBase = (t >> 2) * 128; growBase = lrowBase;
        kBase = (t & 3) * KSLICE; lbfOff = LBF_OFF0;
    } else {
        int t = bx - 640;
        N = NR2; lrowBase = (t >> 2) * 128; growBase = NR0 + NR1 + lrowBase;
        kBase = (t & 3) * KSLICE; lbfOff = LBF_OFF2;
    }
    int zOff = growBase - lrowBase;
    float* dst = layer ? g_xB : g_xA;

    int tid = threadIdx.x;
    int wid = tid >> 5, lane = tid & 31;
    int g = lane >> 2, tg = lane & 3;
    int wm = wid >> 1, wn = wid & 1;     // 4m x 2n warp grid, tile m32n32

    uint32_t smBase = (uint32_t)__cvta_generic_to_shared(sm);

    // ---- ldmatrix lane byte offsets (within stage; +ks*32 bytes per k16 step) ----
    uint32_t aBase[2];
    #pragma unroll
    for (int mt = 0; mt < 2; mt++) {
        int row = wm * 32 + mt * 16 + (lane & 15);
        int col = (lane & 16) ? 8 : 0;
        aBase[mt] = 2u * (AH_OFF + row * SA + col);
    }
    uint32_t bBase[2];
    #pragma unroll
    for (int p = 0; p < 2; p++) {
        int row = wn * 32 + p * 16 + (lane & 7) + ((lane & 16) >> 1);
        int col = (lane & 8) ? 8 : 0;
        bBase[p] = 2u * (BH_OFF + row * SA + col);
    }

    // ---- cp.async loader setup (per chunk: A 16KB + B 8KB; 6 x 16B/thread) ----
    const uint16_t* aSrc[4]; uint32_t aDst[4];
    #pragma unroll
    for (int q = 0; q < 4; q++) {
        int idx = q * 256 + tid;
        int aRow = idx >> 3, aSeg = idx & 7;
        aSrc[q] = g_Lh + lbfOff + (size_t)(lrowBase + aRow) * N + kBase + aSeg * 8;
        aDst[q] = 2u * (AH_OFF + aRow * SA + aSeg * 8);
    }
    const uint16_t* bSrc[2]; uint32_t bDst[2];
    #pragma unroll
    for (int q = 0; q < 2; q++) {
        int idx = q * 256 + tid;
        int bRow = idx >> 3, bSeg = idx & 7;
        bSrc[q] = g_zh + (size_t)bRow * NT + zOff + kBase + bSeg * 8;
        bDst[q] = 2u * (BH_OFF + bRow * SA + bSeg * 8);
    }

    float acc[2][4][4];
    #pragma unroll
    for (int mt = 0; mt < 2; mt++)
        #pragma unroll
        for (int nt = 0; nt < 4; nt++)
            #pragma unroll
            for (int i = 0; i < 4; i++) acc[mt][nt][i] = 0.f;

    int sIssue = 0, sComp = 0;
    int ksOff = wid & 3;   // warp-staggered ks start (de-phases bursts)

    // ---- prologue: issue chunks 0,1,2 ----
    #pragma unroll
    for (int p = 0; p < 3; p++) {
        uint32_t st = smBase + (uint32_t)sIssue * STAGE_BYTES;
        int k0 = p * 64;
        #pragma unroll
        for (int q = 0; q < 4; q++) cp16(st + aDst[q], aSrc[q] + k0);
        #pragma unroll
        for (int q = 0; q < 2; q++) cp16(st + bDst[q], bSrc[q] + k0);
        CP_COMMIT();
        if (++sIssue == NSTAGE) sIssue = 0;
    }

    // ---- mainloop ----
    for (int cI = 0; cI < NCHUNK; cI++) {
        CP_WAIT2();
        __syncthreads();

        if (cI + 3 < NCHUNK) {
            uint32_t st = smBase + (uint32_t)sIssue * STAGE_BYTES;
            int k0 = (cI + 3) * 64;
            #pragma unroll
            for (int q = 0; q < 4; q++) cp16(st + aDst[q], aSrc[q] + k0);
            #pragma unroll
            for (int q = 0; q < 2; q++) cp16(st + bDst[q], bSrc[q] + k0);
        }
        CP_COMMIT();   // unconditional: keeps wait_group accounting correct at tail
        if (++sIssue == NSTAGE) sIssue = 0;

        uint32_t stage = smBase + (uint32_t)sComp * STAGE_BYTES;
        if (++sComp == NSTAGE) sComp = 0;
        #pragma unroll
        for (int ksi = 0; ksi < 4; ksi++) {
            int ks = (ksi + ksOff) & 3;
            uint32_t ah[2][4];
            #pragma unroll
            for (int mt = 0; mt < 2; mt++)
                ldsm_x4(ah[mt][0], ah[mt][1], ah[mt][2], ah[mt][3],
                        stage + aBase[mt] + ks * 32);
            uint32_t bv[4][2];
            #pragma unroll
            for (int p = 0; p < 2; p++)
                ldsm_x4(bv[p * 2][0], bv[p * 2][1], bv[p * 2 + 1][0], bv[p * 2 + 1][1],
                        stage + bBase[p] + ks * 32);
            #pragma unroll
            for (int mt = 0; mt < 2; mt++)
                #pragma unroll
                for (int nt = 0; nt < 4; nt++)
                    mma_f16(acc[mt][nt], ah[mt], bv[nt]);
        }
    }

    // ---- epilogue: dinv row-scale, atomicAdd partial (no relu) ----
    #pragma unroll
    for (int mt = 0; mt < 2; mt++) {
        int row0 = wm * 32 + mt * 16 + g;
        float dv0 = g_dinv[growBase + row0];
        float dv1 = g_dinv[growBase + row0 + 8];
        #pragma unroll
        for (int nt = 0; nt < 4; nt++) {
            int col = wn * 32 + nt * 8 + tg * 2;
            float* c = acc[mt][nt];
            float* p0 = &dst[(size_t)(growBase + row0) * C + col];
            float* p1 = &dst[(size_t)(growBase + row0 + 8) * C + col];
            atomicAdd(p0,     c[0] * dv0);
            atomicAdd(p0 + 1, c[1] * dv0);
            atomicAdd(p1,     c[2] * dv1);
            atomicAdd(p1 + 1, c[3] * dv1);
        }
    }
}

// ============================================================
// readout (relu applied on read of final layer output)
// ============================================================
__global__ void zero_pooled_kernel() {
    int i = blockIdx.x * blockDim.x + threadIdx.x;
    if (i < 3 * NB * C) g_pooled[i] = 0.f;
}

__global__ void pool_kernel(const int* __restrict__ bel0,
                            const int* __restrict__ bel1,
                            const int* __restrict__ bel2) {
    int grow = blockIdx.x;
    int rank, lr;
    if (grow < NR0)            { rank = 0; lr = grow; }
    else if (grow < NR0 + NR1) { rank = 1; lr = grow - NR0; }
    else                       { rank = 2; lr = grow - NR0 - NR1; }
    const int* bel = (rank == 0) ? bel0 : (rank == 1 ? bel1 : bel2);
    int b = bel[lr];
    float v = fmaxf(g_xB[(size_t)grow * C + threadIdx.x], 0.f);
    atomicAdd(&g_pooled[rank * NB * C + b * C + threadIdx.x], v);
}

__global__ void out_kernel(const float* __restrict__ Wr0, const float* __restrict__ br0,
                           const float* __restrict__ Wr1, const float* __restrict__ br1,
                           const float* __restrict__ Wr2, const float* __restrict__ br2,
                           float* __restrict__ out) {
    int b = blockIdx.x;
    int o = threadIdx.x;
    float acc = br0[o] + br1[o] + br2[o];
    const float* Wrs[3] = {Wr0, Wr1, Wr2};
    #pragma unroll
    for (int r = 0; r < 3; r++) {
        const float* Wr = Wrs[r];
        const float* p  = &g_pooled[r * NB * C + b * C];
        #pragma unroll 8
        for (int c = 0; c < C; c++) acc += p[c] * Wr[c * OUTC + o];
    }
    out[b * OUTC + o] = acc;
}

// ============================================================
extern "C" void kernel_launch(void* const* d_in, const int* in_sizes, int n_in,
                              void* d_out, int out_size) {
    const float* x0  = (const float*)d_in[0];
    const float* x1  = (const float*)d_in[1];
    const float* x2  = (const float*)d_in[2];
    const float* L0  = (const float*)d_in[3];
    const float* L1  = (const float*)d_in[4];
    const float* L2  = (const float*)d_in[5];
    const int*   bel0 = (const int*)d_in[6];
    const int*   bel1 = (const int*)d_in[7];
    const int*   bel2 = (const int*)d_in[8];
    const float* W0  = (const float*)d_in[9];
    const float* W1  = (const float*)d_in[10];
    const float* W2  = (const float*)d_in[11];
    const float* Wr0 = (const float*)d_in[12];
    const float* br0 = (const float*)d_in[13];
    const float* Wr1 = (const float*)d_in[14];
    const float* br1 = (const float*)d_in[15];
    const float* Wr2 = (const float*)d_in[16];
    const float* br2 = (const float*)d_in[17];

    cudaFuncSetAttribute(gemm_mma, cudaFuncAttributeMaxDynamicSharedMemorySize, GEMM_SMEM);

    dinv_conv_kernel<<<NT, 128>>>(L0, L1, L2);
    zero_x_kernel<<<(NT * C / 4) / 256, 256>>>();   // zero g_xA + g_xB

    for (int layer = 0; layer < 2; layer++) {
        xw_kernel<<<NT / 32, 128>>>(x0, x1, x2, W0, W1, W2, layer);
        gemm_mma<<<768, 256, GEMM_SMEM>>>(layer);
    }

    zero_pooled_kernel<<<(3 * NB * C + 255) / 256, 256>>>();
    pool_kernel<<<NT, 64>>>(bel0, bel1, bel2);
    out_kernel<<<NB, OUTC>>>(Wr0, br0, Wr1, br1, Wr2, br2, (float*)d_out);
}